// round 12
// baseline (speedup 1.0000x reference)
#include <cuda_runtime.h>
#include <cstdint>
#include <math.h>

// ConvSTFT via windowed FFT-1024 = 16 x 16 x 4, register radix-16,
// real-input packing (two frames per complex FFT), AoS float2 smem,
// table-driven twiddles (no iterated cmul chains).
// CTA: 8 frames = 4 packed FFTs, 64 threads each (256 threads).

#define TLEN   160000
#define NBATCH 32
#define FRAMES 501
#define NBINS  513
#define HOP    320
#define FPC    8
#define PBLK2  1092              // float2 per packed-FFT block (2*1092 mod 32 == 8)

__device__ float  g_win[1024];
__device__ float2 g_twid[1024];  // W_1024^e = e^{-2pi i e/1024}

__global__ void table_kernel() {
    int id = blockIdx.x * 64 + threadIdx.x;
    if (id < 1024) {
        double w = 0.0;
        if (id >= 112 && id < 912)
            w = 0.5 * (1.0 - cos(2.0 * M_PI * (double)(id - 112) / 799.0));
        g_win[id] = (float)w;
    } else {
        int e = id - 1024;
        double ang = 2.0 * M_PI * (double)e / 1024.0;
        g_twid[e] = make_float2((float)cos(ang), (float)(-sin(ang)));
    }
}

__device__ __forceinline__ float2 cadd(float2 a, float2 b) {
    return make_float2(a.x + b.x, a.y + b.y);
}
__device__ __forceinline__ float2 csub(float2 a, float2 b) {
    return make_float2(a.x - b.x, a.y - b.y);
}
__device__ __forceinline__ float2 cmul(float2 a, float2 b) {
    return make_float2(a.x * b.x - a.y * b.y, a.x * b.y + a.y * b.x);
}
__device__ __forceinline__ void r4(float2& a, float2& b, float2& c, float2& d) {
    float2 t0 = cadd(a, c), t1 = csub(a, c), t2 = cadd(b, d), t3 = csub(b, d);
    a = cadd(t0, t2);
    b = make_float2(t1.x + t3.y, t1.y - t3.x);
    c = csub(t0, t2);
    d = make_float2(t1.x - t3.y, t1.y + t3.x);
}
// FFT-16 in regs; freq f lives at slot ((f&3)<<2) | (f>>2).
__device__ __forceinline__ void fft16(float2 v[16]) {
#pragma unroll
    for (int n2 = 0; n2 < 4; n2++) r4(v[n2], v[n2 + 4], v[n2 + 8], v[n2 + 12]);
    const float C8 = 0.70710678118654752f;
    const float c1 = 0.92387953251128674f, s1 = 0.38268343236508977f;
    const float2 W1 = make_float2(c1, -s1),  W2 = make_float2(C8, -C8);
    const float2 W3 = make_float2(s1, -c1),  W4 = make_float2(0.f, -1.f);
    const float2 W6 = make_float2(-C8, -C8), W9 = make_float2(-c1, s1);
    v[5]  = cmul(v[5],  W1); v[6]  = cmul(v[6],  W2); v[7]  = cmul(v[7],  W3);
    v[9]  = cmul(v[9],  W2); v[10] = cmul(v[10], W4); v[11] = cmul(v[11], W6);
    v[13] = cmul(v[13], W3); v[14] = cmul(v[14], W6); v[15] = cmul(v[15], W9);
#pragma unroll
    for (int k1 = 0; k1 < 4; k1++) r4(v[4*k1], v[4*k1+1], v[4*k1+2], v[4*k1+3]);
}
// bin k -> smem slot (stage-C storage permutation, XOR-swizzled for banks)
__device__ __forceinline__ int LOC(int k) {
    const int jg = (k >> 6) & 3;
    return ((k & 15) ^ (jg << 2)) | (jg << 4)
         | (((k >> 4) & 3) << 6) | (((k >> 8) & 3) << 8);
}

__global__ __launch_bounds__(256)
void stft_fft_kernel(const float* __restrict__ x, float* __restrict__ out) {
    extern __shared__ float2 smem[];   // [4][PBLK2]
    const int tid = threadIdx.x;
    const int g   = tid >> 6;          // packed-FFT index 0..3
    const int u   = tid & 63;          // thread within FFT (= n2)
    const int f0  = blockIdx.x * FPC;
    const int b   = blockIdx.y;
    float2* S = smem + g * PBLK2;
    const int fa = f0 + 2 * g, fb = fa + 1;
    const float* xrow = x + (size_t)b * TLEN;
    const bool interior = (blockIdx.x >= 1) && (blockIdx.x <= 61);

    // ---- stage A: load two frames packed, FFT-16 over n1 (stride 64) ----
    float2 v[16];
    if (interior) {
        const float* pa = xrow + fa * HOP - 512 + u;
#pragma unroll
        for (int n1 = 0; n1 < 16; n1++) {
            const float w = g_win[n1 * 64 + u];
            v[n1] = make_float2(pa[n1 * 64] * w, pa[n1 * 64 + HOP] * w);
        }
    } else {
#pragma unroll
        for (int n1 = 0; n1 < 16; n1++) {
            const int p   = n1 * 64 + u;
            const float w = g_win[p];
            const int xia = fa * HOP + p - 512;
            const int xib = xia + HOP;
            float ra = 0.f, rb = 0.f;
            if (fa < FRAMES && xia >= 0 && xia < TLEN) ra = xrow[xia] * w;
            if (fb < FRAMES && xib >= 0 && xib < TLEN) rb = xrow[xib] * w;
            v[n1] = make_float2(ra, rb);
        }
    }
    fft16(v);
    {   // twiddle W_1024^{k1*u} via table; write S[k1*68 + u]
        S[u] = v[0];
#pragma unroll
        for (int k1 = 1; k1 < 16; k1++) {
            const int s = ((k1 & 3) << 2) | (k1 >> 2);
            S[k1 * 68 + u] = cmul(v[s], g_twid[k1 * u]);   // idx <= 945
        }
    }
    __syncthreads();

    // ---- stage B: FFT-16 over m1 (stride 4) ----
    const int k1 = u >> 2, m2 = u & 3;
#pragma unroll
    for (int m1 = 0; m1 < 16; m1++)
        v[m1] = S[k1 * 68 + 4 * m1 + m2];
    __syncthreads();
    fft16(v);
    {   // twiddle W_64^{j1*m2} = W_1024^{16*m2*j1} via table
        const int tw = 16 * m2;
        S[k1 * 4 + m2] = v[0];
#pragma unroll
        for (int j1 = 1; j1 < 16; j1++) {
            const int s = ((j1 & 3) << 2) | (j1 >> 2);
            S[j1 * 64 + k1 * 4 + m2] = cmul(v[s], g_twid[tw * j1]);  // idx <= 720
        }
    }
    __syncthreads();

    // ---- stage C: radix-4 over m2; all 1024 bins to smem (permuted) ----
    const int jg = u & 3, k1c = u >> 2;
    float2 d[4][4];
#pragma unroll
    for (int dj = 0; dj < 4; dj++)
#pragma unroll
        for (int dm = 0; dm < 4; dm++) {     // rotated m2 -> conflict-free
            const int m2r = (jg + dm) & 3;
            d[dj][m2r] = S[(4 * jg + dj) * 64 + k1c * 4 + m2r];
        }
    __syncthreads();
    const int locbase = (k1c ^ (jg << 2)) | (jg << 4);
#pragma unroll
    for (int dj = 0; dj < 4; dj++) {
        r4(d[dj][0], d[dj][1], d[dj][2], d[dj][3]);   // bins kap + 256*j2
#pragma unroll
        for (int j2 = 0; j2 < 4; j2++)
            S[locbase + (dj << 6) + (j2 << 8)] = d[dj][j2];
    }
    __syncthreads();

    // ---- unpack + coalesced store: k < 512 exact, bin 512 by tid<4 ----
    float2* o2 = (float2*)out;
    const int p     = tid & 3;
    const int kbase = tid >> 2;            // 0..63
    const float2* Sp = smem + p * PBLK2;
    const int ffa = f0 + 2 * p;
    const size_t orow = ((size_t)b * NBINS) * FRAMES + ffa;
#pragma unroll
    for (int it = 0; it < 8; it++) {
        const int k  = kbase + 64 * it;    // 0..511
        const int kb = (1024 - k) & 1023;
        const float2 z1 = Sp[LOC(k)];
        const float2 z2 = Sp[LOC(kb)];
        const float2 Xa = make_float2(0.5f * (z1.x + z2.x), 0.5f * (z1.y - z2.y));
        const float2 Xb = make_float2(0.5f * (z1.y + z2.y), 0.5f * (z2.x - z1.x));
        const size_t base = orow + (size_t)k * FRAMES;
        if (interior) {
            o2[base]     = Xa;
            o2[base + 1] = Xb;
        } else {
            if (ffa < FRAMES)     o2[base]     = Xa;
            if (ffa + 1 < FRAMES) o2[base + 1] = Xb;
        }
    }
    if (tid < 4) {                         // bin 512 (self-conjugate)
        const float2 z = smem[tid * PBLK2 + LOC(512)];
        const int ff = f0 + 2 * tid;
        const size_t base = ((size_t)b * NBINS + 512) * FRAMES + ff;
        if (interior) {
            o2[base]     = make_float2(z.x, 0.f);
            o2[base + 1] = make_float2(z.y, 0.f);
        } else {
            if (ff < FRAMES)     o2[base]     = make_float2(z.x, 0.f);
            if (ff + 1 < FRAMES) o2[base + 1] = make_float2(z.y, 0.f);
        }
    }
}

extern "C" void kernel_launch(void* const* d_in, const int* in_sizes, int n_in,
                              void* d_out, int out_size) {
    const float* x = (const float*)d_in[0];
    float* out     = (float*)d_out;

    table_kernel<<<32, 64>>>();

    const int smem_bytes = 4 * PBLK2 * sizeof(float2);   // 34944
    cudaFuncSetAttribute(stft_fft_kernel,
                         cudaFuncAttributeMaxDynamicSharedMemorySize, smem_bytes);
    dim3 grid((FRAMES + FPC - 1) / FPC,   // 63
              NBATCH);                    // 32
    stft_fft_kernel<<<grid, 256, smem_bytes>>>(x, out);
}

// round 13
// speedup vs baseline: 1.1856x; 1.1856x over previous
#include <cuda_runtime.h>
#include <cstdint>
#include <math.h>

// ConvSTFT via windowed FFT-1024 = 16 x 16 x 4, register radix-16,
// real-input packing (two frames per complex FFT), AoS float2 smem,
// in-register twiddles with 4 parallel power chains (depth 5, not 15).
// CTA: 8 frames = 4 packed FFTs, 64 threads each (256 threads).

#define TLEN   160000
#define NBATCH 32
#define FRAMES 501
#define NBINS  513
#define HOP    320
#define FPC    8
#define PBLK2  1092              // float2 per packed-FFT block (2*1092 mod 32 == 8)

__device__ float  g_win[1024];
__device__ float2 g_tw64[64];    // W_1024^e = e^{-2pi i e/1024}

__global__ void table_kernel() {
    int id = blockIdx.x * 64 + threadIdx.x;
    if (id < 1024) {
        double w = 0.0;
        if (id >= 112 && id < 912)
            w = 0.5 * (1.0 - cos(2.0 * M_PI * (double)(id - 112) / 799.0));
        g_win[id] = (float)w;
    } else if (id < 1088) {
        int e = id - 1024;
        double ang = 2.0 * M_PI * (double)e / 1024.0;
        g_tw64[e] = make_float2((float)cos(ang), (float)(-sin(ang)));
    }
}

__device__ __forceinline__ float2 cadd(float2 a, float2 b) {
    return make_float2(a.x + b.x, a.y + b.y);
}
__device__ __forceinline__ float2 csub(float2 a, float2 b) {
    return make_float2(a.x - b.x, a.y - b.y);
}
__device__ __forceinline__ float2 cmul(float2 a, float2 b) {
    return make_float2(a.x * b.x - a.y * b.y, a.x * b.y + a.y * b.x);
}
__device__ __forceinline__ void r4(float2& a, float2& b, float2& c, float2& d) {
    float2 t0 = cadd(a, c), t1 = csub(a, c), t2 = cadd(b, d), t3 = csub(b, d);
    a = cadd(t0, t2);
    b = make_float2(t1.x + t3.y, t1.y - t3.x);
    c = csub(t0, t2);
    d = make_float2(t1.x - t3.y, t1.y + t3.x);
}
// FFT-16 in regs; freq f lives at slot ((f&3)<<2) | (f>>2).
__device__ __forceinline__ void fft16(float2 v[16]) {
#pragma unroll
    for (int n2 = 0; n2 < 4; n2++) r4(v[n2], v[n2 + 4], v[n2 + 8], v[n2 + 12]);
    const float C8 = 0.70710678118654752f;
    const float c1 = 0.92387953251128674f, s1 = 0.38268343236508977f;
    const float2 W1 = make_float2(c1, -s1),  W2 = make_float2(C8, -C8);
    const float2 W3 = make_float2(s1, -c1),  W4 = make_float2(0.f, -1.f);
    const float2 W6 = make_float2(-C8, -C8), W9 = make_float2(-c1, s1);
    v[5]  = cmul(v[5],  W1); v[6]  = cmul(v[6],  W2); v[7]  = cmul(v[7],  W3);
    v[9]  = cmul(v[9],  W2); v[10] = cmul(v[10], W4); v[11] = cmul(v[11], W6);
    v[13] = cmul(v[13], W3); v[14] = cmul(v[14], W6); v[15] = cmul(v[15], W9);
#pragma unroll
    for (int k1 = 0; k1 < 4; k1++) r4(v[4*k1], v[4*k1+1], v[4*k1+2], v[4*k1+3]);
}
// bin k -> smem slot (stage-C storage permutation, XOR-swizzled for banks)
__device__ __forceinline__ int LOC(int k) {
    const int jg = (k >> 6) & 3;
    return ((k & 15) ^ (jg << 2)) | (jg << 4)
         | (((k >> 4) & 3) << 6) | (((k >> 8) & 3) << 8);
}

__global__ __launch_bounds__(256)
void stft_fft_kernel(const float* __restrict__ x, float* __restrict__ out) {
    extern __shared__ float2 smem[];   // [4][PBLK2]
    const int tid = threadIdx.x;
    const int g   = tid >> 6;          // packed-FFT index 0..3
    const int u   = tid & 63;          // thread within FFT (= n2)
    const int f0  = blockIdx.x * FPC;
    const int b   = blockIdx.y;
    float2* S = smem + g * PBLK2;
    const int fa = f0 + 2 * g, fb = fa + 1;
    const float* xrow = x + (size_t)b * TLEN;
    const bool interior = (blockIdx.x >= 1) && (blockIdx.x <= 61);

    // ---- stage A: load two frames packed, FFT-16 over n1 (stride 64) ----
    float2 v[16];
    if (interior) {
        const float* pa = xrow + fa * HOP - 512 + u;
#pragma unroll
        for (int n1 = 0; n1 < 16; n1++) {
            const float w = g_win[n1 * 64 + u];
            v[n1] = make_float2(pa[n1 * 64] * w, pa[n1 * 64 + HOP] * w);
        }
    } else {
#pragma unroll
        for (int n1 = 0; n1 < 16; n1++) {
            const int p   = n1 * 64 + u;
            const float w = g_win[p];
            const int xia = fa * HOP + p - 512;
            const int xib = xia + HOP;
            float ra = 0.f, rb = 0.f;
            if (fa < FRAMES && xia >= 0 && xia < TLEN) ra = xrow[xia] * w;
            if (fb < FRAMES && xib >= 0 && xib < TLEN) rb = xrow[xib] * w;
            v[n1] = make_float2(ra, rb);
        }
    }
    fft16(v);
    {   // twiddle W_1024^{k1*u}; 4 parallel chains stepping by w^4
        const float2 w1 = g_tw64[u];
        const float2 w2 = cmul(w1, w1);
        const float2 w3 = cmul(w2, w1);
        const float2 w4 = cmul(w2, w2);
        S[u] = v[0];
        float2 t1 = w1, t2 = w2, t3 = w3, t4 = w4;
#pragma unroll
        for (int q = 0; q < 4; q++) {    // k1 = 4q+1 .. 4q+4
            const int k1a = 4 * q + 1, k1b = 4 * q + 2,
                      k1c = 4 * q + 3, k1d = 4 * q + 4;
            S[k1a * 68 + u] = cmul(v[((k1a & 3) << 2) | (k1a >> 2)], t1);
            S[k1b * 68 + u] = cmul(v[((k1b & 3) << 2) | (k1b >> 2)], t2);
            S[k1c * 68 + u] = cmul(v[((k1c & 3) << 2) | (k1c >> 2)], t3);
            if (k1d < 16)
                S[k1d * 68 + u] = cmul(v[((k1d & 3) << 2) | (k1d >> 2)], t4);
            if (q < 3) {
                t1 = cmul(t1, w4); t2 = cmul(t2, w4);
                t3 = cmul(t3, w4); t4 = cmul(t4, w4);
            }
        }
    }
    __syncthreads();

    // ---- stage B: FFT-16 over m1 (stride 4) ----
    const int k1 = u >> 2, m2 = u & 3;
#pragma unroll
    for (int m1 = 0; m1 < 16; m1++)
        v[m1] = S[k1 * 68 + 4 * m1 + m2];
    __syncthreads();
    fft16(v);
    {   // twiddle W_64^{j1*m2} = (W_1024^{16*m2})^{j1}; 4 parallel chains
        const float2 w1 = g_tw64[16 * m2];
        const float2 w2 = cmul(w1, w1);
        const float2 w3 = cmul(w2, w1);
        const float2 w4 = cmul(w2, w2);
        S[k1 * 4 + m2] = v[0];
        float2 t1 = w1, t2 = w2, t3 = w3, t4 = w4;
#pragma unroll
        for (int q = 0; q < 4; q++) {
            const int j1a = 4 * q + 1, j1b = 4 * q + 2,
                      j1c = 4 * q + 3, j1d = 4 * q + 4;
            S[j1a * 64 + k1 * 4 + m2] = cmul(v[((j1a & 3) << 2) | (j1a >> 2)], t1);
            S[j1b * 64 + k1 * 4 + m2] = cmul(v[((j1b & 3) << 2) | (j1b >> 2)], t2);
            S[j1c * 64 + k1 * 4 + m2] = cmul(v[((j1c & 3) << 2) | (j1c >> 2)], t3);
            if (j1d < 16)
                S[j1d * 64 + k1 * 4 + m2] = cmul(v[((j1d & 3) << 2) | (j1d >> 2)], t4);
            if (q < 3) {
                t1 = cmul(t1, w4); t2 = cmul(t2, w4);
                t3 = cmul(t3, w4); t4 = cmul(t4, w4);
            }
        }
    }
    __syncthreads();

    // ---- stage C: radix-4 over m2; all 1024 bins to smem (permuted) ----
    const int jg = u & 3, k1c = u >> 2;
    float2 d[4][4];
#pragma unroll
    for (int dj = 0; dj < 4; dj++)
#pragma unroll
        for (int dm = 0; dm < 4; dm++) {     // rotated m2 -> conflict-free
            const int m2r = (jg + dm) & 3;
            d[dj][m2r] = S[(4 * jg + dj) * 64 + k1c * 4 + m2r];
        }
    __syncthreads();
    const int locbase = (k1c ^ (jg << 2)) | (jg << 4);
#pragma unroll
    for (int dj = 0; dj < 4; dj++) {
        r4(d[dj][0], d[dj][1], d[dj][2], d[dj][3]);   // bins kap + 256*j2
#pragma unroll
        for (int j2 = 0; j2 < 4; j2++)
            S[locbase + (dj << 6) + (j2 << 8)] = d[dj][j2];
    }
    __syncthreads();

    // ---- unpack + coalesced store: k < 512 exact, bin 512 by tid<4 ----
    float2* o2 = (float2*)out;
    const int p     = tid & 3;
    const int kbase = tid >> 2;            // 0..63
    const float2* Sp = smem + p * PBLK2;
    const int ffa = f0 + 2 * p;
    const size_t orow = ((size_t)b * NBINS) * FRAMES + ffa;
#pragma unroll
    for (int it = 0; it < 8; it++) {
        const int k  = kbase + 64 * it;    // 0..511
        const int kb = (1024 - k) & 1023;
        const float2 z1 = Sp[LOC(k)];
        const float2 z2 = Sp[LOC(kb)];
        const float2 Xa = make_float2(0.5f * (z1.x + z2.x), 0.5f * (z1.y - z2.y));
        const float2 Xb = make_float2(0.5f * (z1.y + z2.y), 0.5f * (z2.x - z1.x));
        const size_t base = orow + (size_t)k * FRAMES;
        if (interior) {
            o2[base]     = Xa;
            o2[base + 1] = Xb;
        } else {
            if (ffa < FRAMES)     o2[base]     = Xa;
            if (ffa + 1 < FRAMES) o2[base + 1] = Xb;
        }
    }
    if (tid < 4) {                         // bin 512 (self-conjugate)
        const float2 z = smem[tid * PBLK2 + LOC(512)];
        const int ff = f0 + 2 * tid;
        const size_t base = ((size_t)b * NBINS + 512) * FRAMES + ff;
        if (interior) {
            o2[base]     = make_float2(z.x, 0.f);
            o2[base + 1] = make_float2(z.y, 0.f);
        } else {
            if (ff < FRAMES)     o2[base]     = make_float2(z.x, 0.f);
            if (ff + 1 < FRAMES) o2[base + 1] = make_float2(z.y, 0.f);
        }
    }
}

extern "C" void kernel_launch(void* const* d_in, const int* in_sizes, int n_in,
                              void* d_out, int out_size) {
    const float* x = (const float*)d_in[0];
    float* out     = (float*)d_out;

    table_kernel<<<17, 64>>>();

    const int smem_bytes = 4 * PBLK2 * sizeof(float2);   // 34944
    cudaFuncSetAttribute(stft_fft_kernel,
                         cudaFuncAttributeMaxDynamicSharedMemorySize, smem_bytes);
    dim3 grid((FRAMES + FPC - 1) / FPC,   // 63
              NBATCH);                    // 32
    stft_fft_kernel<<<grid, 256, smem_bytes>>>(x, out);
}

// round 14
// speedup vs baseline: 1.2362x; 1.0427x over previous
#include <cuda_runtime.h>
#include <cstdint>
#include <math.h>

// ConvSTFT via windowed FFT-1024 = 16 x 16 x 4, register radix-16,
// real-input packing (two frames per complex FFT), AoS float2 smem,
// in-register twiddles (4 parallel power chains), in-kernel window/twiddle
// generation via MUFU (no table kernel), FFMA-imm butterflies.
// CTA: 8 frames = 4 packed FFTs, 64 threads each (256 threads).

#define TLEN   160000
#define NBATCH 32
#define FRAMES 501
#define NBINS  513
#define HOP    320
#define FPC    8
#define PBLK2  1092              // float2 per packed-FFT block (2*1092 mod 32 == 8)

__device__ __forceinline__ float fadd_(float a, float b) {
    return __fmaf_rn(1.0f, a, b);      // FFMA-imm: rt=1 on fma pipe
}
__device__ __forceinline__ float fsub_(float a, float b) {
    return __fmaf_rn(-1.0f, b, a);
}
__device__ __forceinline__ float2 cadd(float2 a, float2 b) {
    return make_float2(fadd_(a.x, b.x), fadd_(a.y, b.y));
}
__device__ __forceinline__ float2 csub(float2 a, float2 b) {
    return make_float2(fsub_(a.x, b.x), fsub_(a.y, b.y));
}
__device__ __forceinline__ float2 cmul(float2 a, float2 b) {
    return make_float2(a.x * b.x - a.y * b.y, a.x * b.y + a.y * b.x);
}
__device__ __forceinline__ void r4(float2& a, float2& b, float2& c, float2& d) {
    float2 t0 = cadd(a, c), t1 = csub(a, c), t2 = cadd(b, d), t3 = csub(b, d);
    a = cadd(t0, t2);
    b = make_float2(fadd_(t1.x, t3.y), fsub_(t1.y, t3.x));
    c = csub(t0, t2);
    d = make_float2(fsub_(t1.x, t3.y), fadd_(t1.y, t3.x));
}
// FFT-16 in regs; freq f lives at slot ((f&3)<<2) | (f>>2).
__device__ __forceinline__ void fft16(float2 v[16]) {
#pragma unroll
    for (int n2 = 0; n2 < 4; n2++) r4(v[n2], v[n2 + 4], v[n2 + 8], v[n2 + 12]);
    const float C8 = 0.70710678118654752f;
    const float c1 = 0.92387953251128674f, s1 = 0.38268343236508977f;
    const float2 W1 = make_float2(c1, -s1),  W2 = make_float2(C8, -C8);
    const float2 W3 = make_float2(s1, -c1),  W4 = make_float2(0.f, -1.f);
    const float2 W6 = make_float2(-C8, -C8), W9 = make_float2(-c1, s1);
    v[5]  = cmul(v[5],  W1); v[6]  = cmul(v[6],  W2); v[7]  = cmul(v[7],  W3);
    v[9]  = cmul(v[9],  W2); v[10] = cmul(v[10], W4); v[11] = cmul(v[11], W6);
    v[13] = cmul(v[13], W3); v[14] = cmul(v[14], W6); v[15] = cmul(v[15], W9);
#pragma unroll
    for (int k1 = 0; k1 < 4; k1++) r4(v[4*k1], v[4*k1+1], v[4*k1+2], v[4*k1+3]);
}
// bin k -> smem slot (stage-C storage permutation, XOR-swizzled for banks)
__device__ __forceinline__ int LOC(int k) {
    const int jg = (k >> 6) & 3;
    return ((k & 15) ^ (jg << 2)) | (jg << 4)
         | (((k >> 4) & 3) << 6) | (((k >> 8) & 3) << 8);
}

__global__ __launch_bounds__(256)
void stft_fft_kernel(const float* __restrict__ x, float* __restrict__ out) {
    extern __shared__ float2 smem[];   // [4][PBLK2]
    const int tid = threadIdx.x;
    const int g   = tid >> 6;          // packed-FFT index 0..3
    const int u   = tid & 63;          // thread within FFT (= n2)
    const int f0  = blockIdx.x * FPC;
    const int b   = blockIdx.y;
    float2* S = smem + g * PBLK2;
    const int fa = f0 + 2 * g, fb = fa + 1;
    const float* xrow = x + (size_t)b * TLEN;
    const bool interior = (blockIdx.x >= 1) && (blockIdx.x <= 61);

    // ---- stage A: load two frames packed (inline Hann window), FFT-16 ----
    const float WSC = 6.2831853071795864f / 799.0f;
    float2 v[16];
    if (interior) {
        const float* pa = xrow + fa * HOP - 512 + u;
#pragma unroll
        for (int n1 = 0; n1 < 16; n1++) {
            const int p = n1 * 64 + u;
            if (n1 == 0 || n1 == 15) {          // window identically zero
                v[n1] = make_float2(0.f, 0.f);
            } else {
                float w = 0.f;
                if (p >= 112 && p < 912)
                    w = 0.5f - 0.5f * __cosf((float)(p - 112) * WSC);
                v[n1] = make_float2(pa[n1 * 64] * w, pa[n1 * 64 + HOP] * w);
            }
        }
    } else {
#pragma unroll
        for (int n1 = 0; n1 < 16; n1++) {
            const int p = n1 * 64 + u;
            if (n1 == 0 || n1 == 15) {
                v[n1] = make_float2(0.f, 0.f);
            } else {
                float w = 0.f;
                if (p >= 112 && p < 912)
                    w = 0.5f - 0.5f * __cosf((float)(p - 112) * WSC);
                const int xia = fa * HOP + p - 512;
                const int xib = xia + HOP;
                float ra = 0.f, rb = 0.f;
                if (fa < FRAMES && xia >= 0 && xia < TLEN) ra = xrow[xia] * w;
                if (fb < FRAMES && xib >= 0 && xib < TLEN) rb = xrow[xib] * w;
                v[n1] = make_float2(ra, rb);
            }
        }
    }
    fft16(v);
    {   // twiddle W_1024^{k1*u}; 4 parallel chains stepping by w^4
        float sn, cs;
        __sincosf((float)u * (6.2831853071795864f / 1024.0f), &sn, &cs);
        const float2 w1 = make_float2(cs, -sn);
        const float2 w2 = cmul(w1, w1);
        const float2 w3 = cmul(w2, w1);
        const float2 w4 = cmul(w2, w2);
        S[u] = v[0];
        float2 t1 = w1, t2 = w2, t3 = w3, t4 = w4;
#pragma unroll
        for (int q = 0; q < 4; q++) {    // k1 = 4q+1 .. 4q+4
            const int k1a = 4 * q + 1, k1b = 4 * q + 2,
                      k1c = 4 * q + 3, k1d = 4 * q + 4;
            S[k1a * 68 + u] = cmul(v[((k1a & 3) << 2) | (k1a >> 2)], t1);
            S[k1b * 68 + u] = cmul(v[((k1b & 3) << 2) | (k1b >> 2)], t2);
            S[k1c * 68 + u] = cmul(v[((k1c & 3) << 2) | (k1c >> 2)], t3);
            if (k1d < 16)
                S[k1d * 68 + u] = cmul(v[((k1d & 3) << 2) | (k1d >> 2)], t4);
            if (q < 3) {
                t1 = cmul(t1, w4); t2 = cmul(t2, w4);
                t3 = cmul(t3, w4); t4 = cmul(t4, w4);
            }
        }
    }
    __syncthreads();

    // ---- stage B: FFT-16 over m1 (stride 4) ----
    const int k1 = u >> 2, m2 = u & 3;
#pragma unroll
    for (int m1 = 0; m1 < 16; m1++)
        v[m1] = S[k1 * 68 + 4 * m1 + m2];
    __syncthreads();
    fft16(v);
    {   // twiddle W_64^{j1*m2} = (W_1024^{16*m2})^{j1}; 4 parallel chains
        float sn, cs;
        __sincosf((float)m2 * (6.2831853071795864f / 64.0f), &sn, &cs);
        const float2 w1 = make_float2(cs, -sn);
        const float2 w2 = cmul(w1, w1);
        const float2 w3 = cmul(w2, w1);
        const float2 w4 = cmul(w2, w2);
        S[k1 * 4 + m2] = v[0];
        float2 t1 = w1, t2 = w2, t3 = w3, t4 = w4;
#pragma unroll
        for (int q = 0; q < 4; q++) {
            const int j1a = 4 * q + 1, j1b = 4 * q + 2,
                      j1c = 4 * q + 3, j1d = 4 * q + 4;
            S[j1a * 64 + k1 * 4 + m2] = cmul(v[((j1a & 3) << 2) | (j1a >> 2)], t1);
            S[j1b * 64 + k1 * 4 + m2] = cmul(v[((j1b & 3) << 2) | (j1b >> 2)], t2);
            S[j1c * 64 + k1 * 4 + m2] = cmul(v[((j1c & 3) << 2) | (j1c >> 2)], t3);
            if (j1d < 16)
                S[j1d * 64 + k1 * 4 + m2] = cmul(v[((j1d & 3) << 2) | (j1d >> 2)], t4);
            if (q < 3) {
                t1 = cmul(t1, w4); t2 = cmul(t2, w4);
                t3 = cmul(t3, w4); t4 = cmul(t4, w4);
            }
        }
    }
    __syncthreads();

    // ---- stage C: radix-4 over m2; all 1024 bins to smem (permuted) ----
    const int jg = u & 3, k1c = u >> 2;
    float2 d[4][4];
#pragma unroll
    for (int dj = 0; dj < 4; dj++)
#pragma unroll
        for (int dm = 0; dm < 4; dm++) {     // rotated m2 -> conflict-free
            const int m2r = (jg + dm) & 3;
            d[dj][m2r] = S[(4 * jg + dj) * 64 + k1c * 4 + m2r];
        }
    __syncthreads();
    const int locbase = (k1c ^ (jg << 2)) | (jg << 4);
#pragma unroll
    for (int dj = 0; dj < 4; dj++) {
        r4(d[dj][0], d[dj][1], d[dj][2], d[dj][3]);   // bins kap + 256*j2
#pragma unroll
        for (int j2 = 0; j2 < 4; j2++)
            S[locbase + (dj << 6) + (j2 << 8)] = d[dj][j2];
    }
    __syncthreads();

    // ---- unpack + coalesced store (32-bit addressing) ----
    float2* o2 = (float2*)out;
    const int p     = tid & 3;
    const int kbase = tid >> 2;            // 0..63
    const float2* Sp = smem + p * PBLK2;
    const int ffa = f0 + 2 * p;
    const unsigned orow = (unsigned)b * (NBINS * FRAMES) + (unsigned)ffa;
#pragma unroll
    for (int it = 0; it < 8; it++) {
        const int k  = kbase + 64 * it;    // 0..511
        const int kb = (1024 - k) & 1023;
        const float2 z1 = Sp[LOC(k)];
        const float2 z2 = Sp[LOC(kb)];
        const float2 Xa = make_float2(0.5f * (z1.x + z2.x), 0.5f * (z1.y - z2.y));
        const float2 Xb = make_float2(0.5f * (z1.y + z2.y), 0.5f * (z2.x - z1.x));
        const unsigned base = orow + (unsigned)k * FRAMES;
        if (interior) {
            o2[base]     = Xa;
            o2[base + 1] = Xb;
        } else {
            if (ffa < FRAMES)     o2[base]     = Xa;
            if (ffa + 1 < FRAMES) o2[base + 1] = Xb;
        }
    }
    if (tid < 4) {                         // bin 512 (self-conjugate)
        const float2 z = smem[tid * PBLK2 + LOC(512)];
        const int ff = f0 + 2 * tid;
        const unsigned base = (unsigned)b * (NBINS * FRAMES)
                            + 512u * FRAMES + (unsigned)ff;
        if (interior) {
            o2[base]     = make_float2(z.x, 0.f);
            o2[base + 1] = make_float2(z.y, 0.f);
        } else {
            if (ff < FRAMES)     o2[base]     = make_float2(z.x, 0.f);
            if (ff + 1 < FRAMES) o2[base + 1] = make_float2(z.y, 0.f);
        }
    }
}

extern "C" void kernel_launch(void* const* d_in, const int* in_sizes, int n_in,
                              void* d_out, int out_size) {
    const float* x = (const float*)d_in[0];
    float* out     = (float*)d_out;

    const int smem_bytes = 4 * PBLK2 * sizeof(float2);   // 34944
    cudaFuncSetAttribute(stft_fft_kernel,
                         cudaFuncAttributeMaxDynamicSharedMemorySize, smem_bytes);
    dim3 grid((FRAMES + FPC - 1) / FPC,   // 63
              NBATCH);                    // 32
    stft_fft_kernel<<<grid, 256, smem_bytes>>>(x, out);
}

// round 15
// speedup vs baseline: 1.3647x; 1.1040x over previous
#include <cuda_runtime.h>
#include <cstdint>
#include <math.h>

// ConvSTFT via windowed FFT-1024 = 16 x 16 x 4, register radix-16,
// real-input packing (two frames per complex FFT), AoS float2 smem,
// in-register twiddles (4 parallel power chains), in-kernel window/twiddle
// via MUFU, packed fma.rn.f32x2 butterflies (FFMA2).
// CTA: 8 frames = 4 packed FFTs, 64 threads each (256 threads).

#define TLEN   160000
#define NBATCH 32
#define FRAMES 501
#define NBINS  513
#define HOP    320
#define FPC    8
#define PBLK2  1092              // float2 per packed-FFT block (2*1092 mod 32 == 8)

// packed complex add/sub via fma.rn.f32x2 (exact: a*1+b / b*(-1)+a)
__device__ __forceinline__ float2 padd(float2 a, float2 b) {
    float2 r;
    asm("{\n\t.reg .b64 pa, pb, pr, k1;\n\t"
        "mov.b64 k1, 0x3F8000003F800000;\n\t"
        "mov.b64 pa, {%2, %3};\n\t"
        "mov.b64 pb, {%4, %5};\n\t"
        "fma.rn.f32x2 pr, pa, k1, pb;\n\t"
        "mov.b64 {%0, %1}, pr;\n\t}"
        : "=f"(r.x), "=f"(r.y)
        : "f"(a.x), "f"(a.y), "f"(b.x), "f"(b.y));
    return r;
}
__device__ __forceinline__ float2 psub(float2 a, float2 b) {
    float2 r;
    asm("{\n\t.reg .b64 pa, pb, pr, kn;\n\t"
        "mov.b64 kn, 0xBF800000BF800000;\n\t"
        "mov.b64 pa, {%2, %3};\n\t"
        "mov.b64 pb, {%4, %5};\n\t"
        "fma.rn.f32x2 pr, pb, kn, pa;\n\t"
        "mov.b64 {%0, %1}, pr;\n\t}"
        : "=f"(r.x), "=f"(r.y)
        : "f"(a.x), "f"(a.y), "f"(b.x), "f"(b.y));
    return r;
}
__device__ __forceinline__ float2 cmul(float2 a, float2 b) {
    return make_float2(a.x * b.x - a.y * b.y, a.x * b.y + a.y * b.x);
}
__device__ __forceinline__ void r4(float2& a, float2& b, float2& c, float2& d) {
    float2 t0 = padd(a, c), t1 = psub(a, c), t2 = padd(b, d), t3 = psub(b, d);
    a = padd(t0, t2);
    c = psub(t0, t2);
    b = make_float2(t1.x + t3.y, t1.y - t3.x);
    d = make_float2(t1.x - t3.y, t1.y + t3.x);
}
// FFT-16 in regs; freq f lives at slot ((f&3)<<2) | (f>>2).
__device__ __forceinline__ void fft16(float2 v[16]) {
#pragma unroll
    for (int n2 = 0; n2 < 4; n2++) r4(v[n2], v[n2 + 4], v[n2 + 8], v[n2 + 12]);
    const float C8 = 0.70710678118654752f;
    const float c1 = 0.92387953251128674f, s1 = 0.38268343236508977f;
    const float2 W1 = make_float2(c1, -s1),  W2 = make_float2(C8, -C8);
    const float2 W3 = make_float2(s1, -c1),  W4 = make_float2(0.f, -1.f);
    const float2 W6 = make_float2(-C8, -C8), W9 = make_float2(-c1, s1);
    v[5]  = cmul(v[5],  W1); v[6]  = cmul(v[6],  W2); v[7]  = cmul(v[7],  W3);
    v[9]  = cmul(v[9],  W2); v[10] = cmul(v[10], W4); v[11] = cmul(v[11], W6);
    v[13] = cmul(v[13], W3); v[14] = cmul(v[14], W6); v[15] = cmul(v[15], W9);
#pragma unroll
    for (int k1 = 0; k1 < 4; k1++) r4(v[4*k1], v[4*k1+1], v[4*k1+2], v[4*k1+3]);
}
// bin k -> smem slot (stage-C storage permutation, XOR-swizzled for banks)
__device__ __forceinline__ int LOC(int k) {
    const int jg = (k >> 6) & 3;
    return ((k & 15) ^ (jg << 2)) | (jg << 4)
         | (((k >> 4) & 3) << 6) | (((k >> 8) & 3) << 8);
}

__global__ __launch_bounds__(256)
void stft_fft_kernel(const float* __restrict__ x, float* __restrict__ out) {
    extern __shared__ float2 smem[];   // [4][PBLK2]
    const int tid = threadIdx.x;
    const int g   = tid >> 6;          // packed-FFT index 0..3
    const int u   = tid & 63;          // thread within FFT (= n2)
    const int f0  = blockIdx.x * FPC;
    const int b   = blockIdx.y;
    float2* S = smem + g * PBLK2;
    const int fa = f0 + 2 * g, fb = fa + 1;
    const float* xrow = x + (size_t)b * TLEN;
    const bool interior = (blockIdx.x >= 1) && (blockIdx.x <= 61);

    // ---- stage A: load two frames packed (inline Hann window), FFT-16 ----
    const float WSC = 6.2831853071795864f / 799.0f;
    float2 v[16];
    if (interior) {
        const float* pa = xrow + fa * HOP - 512 + u;
#pragma unroll
        for (int n1 = 0; n1 < 16; n1++) {
            const int p = n1 * 64 + u;
            if (n1 == 0 || n1 == 15) {          // window identically zero
                v[n1] = make_float2(0.f, 0.f);
            } else {
                float w = 0.f;
                if (p >= 112 && p < 912)
                    w = 0.5f - 0.5f * __cosf((float)(p - 112) * WSC);
                v[n1] = make_float2(pa[n1 * 64] * w, pa[n1 * 64 + HOP] * w);
            }
        }
    } else {
#pragma unroll
        for (int n1 = 0; n1 < 16; n1++) {
            const int p = n1 * 64 + u;
            if (n1 == 0 || n1 == 15) {
                v[n1] = make_float2(0.f, 0.f);
            } else {
                float w = 0.f;
                if (p >= 112 && p < 912)
                    w = 0.5f - 0.5f * __cosf((float)(p - 112) * WSC);
                const int xia = fa * HOP + p - 512;
                const int xib = xia + HOP;
                float ra = 0.f, rb = 0.f;
                if (fa < FRAMES && xia >= 0 && xia < TLEN) ra = xrow[xia] * w;
                if (fb < FRAMES && xib >= 0 && xib < TLEN) rb = xrow[xib] * w;
                v[n1] = make_float2(ra, rb);
            }
        }
    }
    fft16(v);
    {   // twiddle W_1024^{k1*u}; 4 parallel chains stepping by w^4
        float sn, cs;
        __sincosf((float)u * (6.2831853071795864f / 1024.0f), &sn, &cs);
        const float2 w1 = make_float2(cs, -sn);
        const float2 w2 = cmul(w1, w1);
        const float2 w3 = cmul(w2, w1);
        const float2 w4 = cmul(w2, w2);
        S[u] = v[0];
        float2 t1 = w1, t2 = w2, t3 = w3, t4 = w4;
#pragma unroll
        for (int q = 0; q < 4; q++) {    // k1 = 4q+1 .. 4q+4
            const int k1a = 4 * q + 1, k1b = 4 * q + 2,
                      k1c = 4 * q + 3, k1d = 4 * q + 4;
            S[k1a * 68 + u] = cmul(v[((k1a & 3) << 2) | (k1a >> 2)], t1);
            S[k1b * 68 + u] = cmul(v[((k1b & 3) << 2) | (k1b >> 2)], t2);
            S[k1c * 68 + u] = cmul(v[((k1c & 3) << 2) | (k1c >> 2)], t3);
            if (k1d < 16)
                S[k1d * 68 + u] = cmul(v[((k1d & 3) << 2) | (k1d >> 2)], t4);
            if (q < 3) {
                t1 = cmul(t1, w4); t2 = cmul(t2, w4);
                t3 = cmul(t3, w4); t4 = cmul(t4, w4);
            }
        }
    }
    __syncthreads();

    // ---- stage B: FFT-16 over m1 (stride 4) ----
    const int k1 = u >> 2, m2 = u & 3;
#pragma unroll
    for (int m1 = 0; m1 < 16; m1++)
        v[m1] = S[k1 * 68 + 4 * m1 + m2];
    __syncthreads();
    fft16(v);
    {   // twiddle W_64^{j1*m2} = (W_1024^{16*m2})^{j1}; 4 parallel chains
        float sn, cs;
        __sincosf((float)m2 * (6.2831853071795864f / 64.0f), &sn, &cs);
        const float2 w1 = make_float2(cs, -sn);
        const float2 w2 = cmul(w1, w1);
        const float2 w3 = cmul(w2, w1);
        const float2 w4 = cmul(w2, w2);
        S[k1 * 4 + m2] = v[0];
        float2 t1 = w1, t2 = w2, t3 = w3, t4 = w4;
#pragma unroll
        for (int q = 0; q < 4; q++) {
            const int j1a = 4 * q + 1, j1b = 4 * q + 2,
                      j1c = 4 * q + 3, j1d = 4 * q + 4;
            S[j1a * 64 + k1 * 4 + m2] = cmul(v[((j1a & 3) << 2) | (j1a >> 2)], t1);
            S[j1b * 64 + k1 * 4 + m2] = cmul(v[((j1b & 3) << 2) | (j1b >> 2)], t2);
            S[j1c * 64 + k1 * 4 + m2] = cmul(v[((j1c & 3) << 2) | (j1c >> 2)], t3);
            if (j1d < 16)
                S[j1d * 64 + k1 * 4 + m2] = cmul(v[((j1d & 3) << 2) | (j1d >> 2)], t4);
            if (q < 3) {
                t1 = cmul(t1, w4); t2 = cmul(t2, w4);
                t3 = cmul(t3, w4); t4 = cmul(t4, w4);
            }
        }
    }
    __syncthreads();

    // ---- stage C: radix-4 over m2; all 1024 bins to smem (permuted) ----
    const int jg = u & 3, k1c = u >> 2;
    float2 d[4][4];
#pragma unroll
    for (int dj = 0; dj < 4; dj++)
#pragma unroll
        for (int dm = 0; dm < 4; dm++) {     // rotated m2 -> conflict-free
            const int m2r = (jg + dm) & 3;
            d[dj][m2r] = S[(4 * jg + dj) * 64 + k1c * 4 + m2r];
        }
    __syncthreads();
    const int locbase = (k1c ^ (jg << 2)) | (jg << 4);
#pragma unroll
    for (int dj = 0; dj < 4; dj++) {
        r4(d[dj][0], d[dj][1], d[dj][2], d[dj][3]);   // bins kap + 256*j2
#pragma unroll
        for (int j2 = 0; j2 < 4; j2++)
            S[locbase + (dj << 6) + (j2 << 8)] = d[dj][j2];
    }
    __syncthreads();

    // ---- unpack + coalesced store (32-bit addressing) ----
    float2* o2 = (float2*)out;
    const int p     = tid & 3;
    const int kbase = tid >> 2;            // 0..63
    const float2* Sp = smem + p * PBLK2;
    const int ffa = f0 + 2 * p;
    const unsigned orow = (unsigned)b * (NBINS * FRAMES) + (unsigned)ffa;
#pragma unroll
    for (int it = 0; it < 8; it++) {
        const int k  = kbase + 64 * it;    // 0..511
        const int kb = (1024 - k) & 1023;
        const float2 z1 = Sp[LOC(k)];
        const float2 z2 = Sp[LOC(kb)];
        const float2 Xa = make_float2(0.5f * (z1.x + z2.x), 0.5f * (z1.y - z2.y));
        const float2 Xb = make_float2(0.5f * (z1.y + z2.y), 0.5f * (z2.x - z1.x));
        const unsigned base = orow + (unsigned)k * FRAMES;
        if (interior) {
            o2[base]     = Xa;
            o2[base + 1] = Xb;
        } else {
            if (ffa < FRAMES)     o2[base]     = Xa;
            if (ffa + 1 < FRAMES) o2[base + 1] = Xb;
        }
    }
    if (tid < 4) {                         // bin 512 (self-conjugate)
        const float2 z = smem[tid * PBLK2 + LOC(512)];
        const int ff = f0 + 2 * tid;
        const unsigned base = (unsigned)b * (NBINS * FRAMES)
                            + 512u * FRAMES + (unsigned)ff;
        if (interior) {
            o2[base]     = make_float2(z.x, 0.f);
            o2[base + 1] = make_float2(z.y, 0.f);
        } else {
            if (ff < FRAMES)     o2[base]     = make_float2(z.x, 0.f);
            if (ff + 1 < FRAMES) o2[base + 1] = make_float2(z.y, 0.f);
        }
    }
}

extern "C" void kernel_launch(void* const* d_in, const int* in_sizes, int n_in,
                              void* d_out, int out_size) {
    const float* x = (const float*)d_in[0];
    float* out     = (float*)d_out;

    const int smem_bytes = 4 * PBLK2 * sizeof(float2);   // 34944
    cudaFuncSetAttribute(stft_fft_kernel,
                         cudaFuncAttributeMaxDynamicSharedMemorySize, smem_bytes);
    dim3 grid((FRAMES + FPC - 1) / FPC,   // 63
              NBATCH);                    // 32
    stft_fft_kernel<<<grid, 256, smem_bytes>>>(x, out);
}

// round 16
// speedup vs baseline: 1.4396x; 1.0548x over previous
#include <cuda_runtime.h>
#include <cstdint>
#include <math.h>

// ConvSTFT via windowed FFT-1024 = 16 x 16 x 4, register radix-16,
// real-input packing (two frames per complex FFT), AoS float2 smem,
// in-register twiddles (4 parallel power chains), in-kernel window/twiddle
// via MUFU, FULLY packed fma.rn.f32x2 butterflies + packed epilogue.
// CTA: 8 frames = 4 packed FFTs, 64 threads each (256 threads).

#define TLEN   160000
#define NBATCH 32
#define FRAMES 501
#define NBINS  513
#define HOP    320
#define FPC    8
#define PBLK2  1092              // float2 per packed-FFT block (2*1092 mod 32 == 8)

#define K_PP1  0x3F8000003F800000ULL   // (+1, +1)
#define K_MM1  0xBF800000BF800000ULL   // (-1, -1)
#define K_PM1  0xBF8000003F800000ULL   // (lo +1, hi -1)
#define K_MP1  0x3F800000BF800000ULL   // (lo -1, hi +1)
#define K_PPH  0x3F0000003F000000ULL   // (+0.5, +0.5)
#define K_PMH  0xBF0000003F000000ULL   // (lo +0.5, hi -0.5)

// r = a*k + c, packed f32x2
__device__ __forceinline__ float2 pfma1(float2 a, unsigned long long k, float2 c) {
    float2 r;
    asm("{\n\t.reg .b64 pa, pc, pr;\n\t"
        "mov.b64 pa, {%2, %3};\n\t"
        "mov.b64 pc, {%4, %5};\n\t"
        "fma.rn.f32x2 pr, pa, %6, pc;\n\t"
        "mov.b64 {%0, %1}, pr;\n\t}"
        : "=f"(r.x), "=f"(r.y)
        : "f"(a.x), "f"(a.y), "f"(c.x), "f"(c.y), "l"(k));
    return r;
}
// r = a*ka + b*kb, packed (mul + fma)
__device__ __forceinline__ float2 pcomb(float2 a, unsigned long long ka,
                                        float2 b, unsigned long long kb) {
    float2 r;
    asm("{\n\t.reg .b64 pa, pb, pt, pr;\n\t"
        "mov.b64 pa, {%2, %3};\n\t"
        "mov.b64 pb, {%4, %5};\n\t"
        "mul.rn.f32x2 pt, pb, %7;\n\t"
        "fma.rn.f32x2 pr, pa, %6, pt;\n\t"
        "mov.b64 {%0, %1}, pr;\n\t}"
        : "=f"(r.x), "=f"(r.y)
        : "f"(a.x), "f"(a.y), "f"(b.x), "f"(b.y), "l"(ka), "l"(kb));
    return r;
}
__device__ __forceinline__ float2 padd(float2 a, float2 b) { return pfma1(a, K_PP1, b); }
__device__ __forceinline__ float2 psub(float2 a, float2 b) { return pfma1(b, K_MM1, a); }
__device__ __forceinline__ float2 cmul(float2 a, float2 b) {
    return make_float2(a.x * b.x - a.y * b.y, a.x * b.y + a.y * b.x);
}
__device__ __forceinline__ void r4(float2& a, float2& b, float2& c, float2& d) {
    float2 t0 = padd(a, c), t1 = psub(a, c), t2 = padd(b, d), t3 = psub(b, d);
    a = padd(t0, t2);
    c = psub(t0, t2);
    const float2 t3s = make_float2(t3.y, t3.x);   // free rename
    b = pfma1(t3s, K_PM1, t1);    // (t1.x + t3.y, t1.y - t3.x)
    d = pfma1(t3s, K_MP1, t1);    // (t1.x - t3.y, t1.y + t3.x)
}
// FFT-16 in regs; freq f lives at slot ((f&3)<<2) | (f>>2).
__device__ __forceinline__ void fft16(float2 v[16]) {
#pragma unroll
    for (int n2 = 0; n2 < 4; n2++) r4(v[n2], v[n2 + 4], v[n2 + 8], v[n2 + 12]);
    const float C8 = 0.70710678118654752f;
    const float c1 = 0.92387953251128674f, s1 = 0.38268343236508977f;
    const float2 W1 = make_float2(c1, -s1),  W2 = make_float2(C8, -C8);
    const float2 W3 = make_float2(s1, -c1),  W4 = make_float2(0.f, -1.f);
    const float2 W6 = make_float2(-C8, -C8), W9 = make_float2(-c1, s1);
    v[5]  = cmul(v[5],  W1); v[6]  = cmul(v[6],  W2); v[7]  = cmul(v[7],  W3);
    v[9]  = cmul(v[9],  W2); v[10] = cmul(v[10], W4); v[11] = cmul(v[11], W6);
    v[13] = cmul(v[13], W3); v[14] = cmul(v[14], W6); v[15] = cmul(v[15], W9);
#pragma unroll
    for (int k1 = 0; k1 < 4; k1++) r4(v[4*k1], v[4*k1+1], v[4*k1+2], v[4*k1+3]);
}
// bin k -> smem slot (stage-C storage permutation, XOR-swizzled for banks)
__device__ __forceinline__ int LOC(int k) {
    const int jg = (k >> 6) & 3;
    return ((k & 15) ^ (jg << 2)) | (jg << 4)
         | (((k >> 4) & 3) << 6) | (((k >> 8) & 3) << 8);
}

__global__ __launch_bounds__(256)
void stft_fft_kernel(const float* __restrict__ x, float* __restrict__ out) {
    extern __shared__ float2 smem[];   // [4][PBLK2]
    const int tid = threadIdx.x;
    const int g   = tid >> 6;          // packed-FFT index 0..3
    const int u   = tid & 63;          // thread within FFT (= n2)
    const int f0  = blockIdx.x * FPC;
    const int b   = blockIdx.y;
    float2* S = smem + g * PBLK2;
    const int fa = f0 + 2 * g, fb = fa + 1;
    const float* xrow = x + (size_t)b * TLEN;
    const bool interior = (blockIdx.x >= 1) && (blockIdx.x <= 61);

    // ---- stage A: load two frames packed (inline Hann window), FFT-16 ----
    const float WSC = 6.2831853071795864f / 799.0f;
    float2 v[16];
    if (interior) {
        const float* pa = xrow + fa * HOP - 512 + u;
#pragma unroll
        for (int n1 = 0; n1 < 16; n1++) {
            const int p = n1 * 64 + u;
            if (n1 == 0 || n1 == 15) {          // window identically zero
                v[n1] = make_float2(0.f, 0.f);
            } else {
                float w = 0.f;
                if (p >= 112 && p < 912)
                    w = 0.5f - 0.5f * __cosf((float)(p - 112) * WSC);
                v[n1] = make_float2(pa[n1 * 64] * w, pa[n1 * 64 + HOP] * w);
            }
        }
    } else {
#pragma unroll
        for (int n1 = 0; n1 < 16; n1++) {
            const int p = n1 * 64 + u;
            if (n1 == 0 || n1 == 15) {
                v[n1] = make_float2(0.f, 0.f);
            } else {
                float w = 0.f;
                if (p >= 112 && p < 912)
                    w = 0.5f - 0.5f * __cosf((float)(p - 112) * WSC);
                const int xia = fa * HOP + p - 512;
                const int xib = xia + HOP;
                float ra = 0.f, rb = 0.f;
                if (fa < FRAMES && xia >= 0 && xia < TLEN) ra = xrow[xia] * w;
                if (fb < FRAMES && xib >= 0 && xib < TLEN) rb = xrow[xib] * w;
                v[n1] = make_float2(ra, rb);
            }
        }
    }
    fft16(v);
    {   // twiddle W_1024^{k1*u}; 4 parallel chains stepping by w^4
        float sn, cs;
        __sincosf((float)u * (6.2831853071795864f / 1024.0f), &sn, &cs);
        const float2 w1 = make_float2(cs, -sn);
        const float2 w2 = cmul(w1, w1);
        const float2 w3 = cmul(w2, w1);
        const float2 w4 = cmul(w2, w2);
        S[u] = v[0];
        float2 t1 = w1, t2 = w2, t3 = w3, t4 = w4;
#pragma unroll
        for (int q = 0; q < 4; q++) {    // k1 = 4q+1 .. 4q+4
            const int k1a = 4 * q + 1, k1b = 4 * q + 2,
                      k1c = 4 * q + 3, k1d = 4 * q + 4;
            S[k1a * 68 + u] = cmul(v[((k1a & 3) << 2) | (k1a >> 2)], t1);
            S[k1b * 68 + u] = cmul(v[((k1b & 3) << 2) | (k1b >> 2)], t2);
            S[k1c * 68 + u] = cmul(v[((k1c & 3) << 2) | (k1c >> 2)], t3);
            if (k1d < 16)
                S[k1d * 68 + u] = cmul(v[((k1d & 3) << 2) | (k1d >> 2)], t4);
            if (q < 3) {
                t1 = cmul(t1, w4); t2 = cmul(t2, w4);
                t3 = cmul(t3, w4); t4 = cmul(t4, w4);
            }
        }
    }
    __syncthreads();

    // ---- stage B: FFT-16 over m1 (stride 4) ----
    const int k1 = u >> 2, m2 = u & 3;
#pragma unroll
    for (int m1 = 0; m1 < 16; m1++)
        v[m1] = S[k1 * 68 + 4 * m1 + m2];
    __syncthreads();
    fft16(v);
    {   // twiddle W_64^{j1*m2} = (W_1024^{16*m2})^{j1}; 4 parallel chains
        float sn, cs;
        __sincosf((float)m2 * (6.2831853071795864f / 64.0f), &sn, &cs);
        const float2 w1 = make_float2(cs, -sn);
        const float2 w2 = cmul(w1, w1);
        const float2 w3 = cmul(w2, w1);
        const float2 w4 = cmul(w2, w2);
        S[k1 * 4 + m2] = v[0];
        float2 t1 = w1, t2 = w2, t3 = w3, t4 = w4;
#pragma unroll
        for (int q = 0; q < 4; q++) {
            const int j1a = 4 * q + 1, j1b = 4 * q + 2,
                      j1c = 4 * q + 3, j1d = 4 * q + 4;
            S[j1a * 64 + k1 * 4 + m2] = cmul(v[((j1a & 3) << 2) | (j1a >> 2)], t1);
            S[j1b * 64 + k1 * 4 + m2] = cmul(v[((j1b & 3) << 2) | (j1b >> 2)], t2);
            S[j1c * 64 + k1 * 4 + m2] = cmul(v[((j1c & 3) << 2) | (j1c >> 2)], t3);
            if (j1d < 16)
                S[j1d * 64 + k1 * 4 + m2] = cmul(v[((j1d & 3) << 2) | (j1d >> 2)], t4);
            if (q < 3) {
                t1 = cmul(t1, w4); t2 = cmul(t2, w4);
                t3 = cmul(t3, w4); t4 = cmul(t4, w4);
            }
        }
    }
    __syncthreads();

    // ---- stage C: radix-4 over m2; all 1024 bins to smem (permuted) ----
    const int jg = u & 3, k1c = u >> 2;
    float2 d[4][4];
#pragma unroll
    for (int dj = 0; dj < 4; dj++)
#pragma unroll
        for (int dm = 0; dm < 4; dm++) {     // rotated m2 -> conflict-free
            const int m2r = (jg + dm) & 3;
            d[dj][m2r] = S[(4 * jg + dj) * 64 + k1c * 4 + m2r];
        }
    __syncthreads();
    const int locbase = (k1c ^ (jg << 2)) | (jg << 4);
#pragma unroll
    for (int dj = 0; dj < 4; dj++) {
        r4(d[dj][0], d[dj][1], d[dj][2], d[dj][3]);   // bins kap + 256*j2
#pragma unroll
        for (int j2 = 0; j2 < 4; j2++)
            S[locbase + (dj << 6) + (j2 << 8)] = d[dj][j2];
    }
    __syncthreads();

    // ---- unpack (packed f32x2) + coalesced store (32-bit addressing) ----
    float2* o2 = (float2*)out;
    const int p     = tid & 3;
    const int kbase = tid >> 2;            // 0..63
    const float2* Sp = smem + p * PBLK2;
    const int ffa = f0 + 2 * p;
    const unsigned orow = (unsigned)b * (NBINS * FRAMES) + (unsigned)ffa;
#pragma unroll
    for (int it = 0; it < 8; it++) {
        const int k  = kbase + 64 * it;    // 0..511
        const int kb = (1024 - k) & 1023;
        const float2 z1 = Sp[LOC(k)];
        const float2 z2 = Sp[LOC(kb)];
        // Xa = z1*(.5,.5) + z2*(.5,-.5);  Xb = sw(z1)*(.5,-.5) + sw(z2)*(.5,.5)
        const float2 Xa = pcomb(z1, K_PPH, z2, K_PMH);
        const float2 Xb = pcomb(make_float2(z1.y, z1.x), K_PMH,
                                make_float2(z2.y, z2.x), K_PPH);
        const unsigned base = orow + (unsigned)k * FRAMES;
        if (interior) {
            o2[base]     = Xa;
            o2[base + 1] = Xb;
        } else {
            if (ffa < FRAMES)     o2[base]     = Xa;
            if (ffa + 1 < FRAMES) o2[base + 1] = Xb;
        }
    }
    if (tid < 4) {                         // bin 512 (self-conjugate)
        const float2 z = smem[tid * PBLK2 + LOC(512)];
        const int ff = f0 + 2 * tid;
        const unsigned base = (unsigned)b * (NBINS * FRAMES)
                            + 512u * FRAMES + (unsigned)ff;
        if (interior) {
            o2[base]     = make_float2(z.x, 0.f);
            o2[base + 1] = make_float2(z.y, 0.f);
        } else {
            if (ff < FRAMES)     o2[base]     = make_float2(z.x, 0.f);
            if (ff + 1 < FRAMES) o2[base + 1] = make_float2(z.y, 0.f);
        }
    }
}

extern "C" void kernel_launch(void* const* d_in, const int* in_sizes, int n_in,
                              void* d_out, int out_size) {
    const float* x = (const float*)d_in[0];
    float* out     = (float*)d_out;

    const int smem_bytes = 4 * PBLK2 * sizeof(float2);   // 34944
    cudaFuncSetAttribute(stft_fft_kernel,
                         cudaFuncAttributeMaxDynamicSharedMemorySize, smem_bytes);
    dim3 grid((FRAMES + FPC - 1) / FPC,   // 63
              NBATCH);                    // 32
    stft_fft_kernel<<<grid, 256, smem_bytes>>>(x, out);
}